// round 2
// baseline (speedup 1.0000x reference)
#include <cuda_runtime.h>
#include <math.h>
#include <stdint.h>

// ---------------- problem constants ----------------
#define BB      4
#define LL      256
#define DD      768
#define NH      12
#define HDIM    64
#define NSTEPS  6
#define SMAX    (LL * NSTEPS)      // 1536
#define NC      50257
#define SLOTS   (NSTEPS + 1)       // 7

// ---------------- device scratch (no runtime alloc allowed) ----------------
__device__ float g_h   [BB * LL * SLOTS * DD];   // slot buffer [B,L,7,D]
__device__ float g_X   [BB * SMAX * DD];         // layer input  (and final layer output)
__device__ float g_QKV [BB * SMAX * 3 * DD];
__device__ float g_AT  [BB * SMAX * DD];         // attention out / ff2 out
__device__ float g_X1  [BB * SMAX * DD];         // post-LN1
__device__ float g_F   [BB * SMAX * DD];         // proj out / ff1 out
__device__ float g_LAST[BB * LL * DD];

// ---------------- small elementwise kernels ----------------
__global__ void embed_kernel(const int* __restrict__ x, const float* __restrict__ emb,
                             const float* __restrict__ pos, float* __restrict__ h)
{
    int r = blockIdx.x;                 // b*L + l
    int l = r % LL;
    int tok = x[r];
    const float* e = emb + (size_t)tok * DD;
    const float* p = pos + (size_t)l * DD;
    float* dst = h + (size_t)r * SLOTS * DD;    // slot 0
    for (int d = threadIdx.x; d < DD; d += blockDim.x)
        dst[d] = e[d] + p[d];
}

__global__ void timeadd_kernel(float* __restrict__ h, const float* __restrict__ te_all, int step)
{
    int r = blockIdx.x;                 // b*L + l
    float* dst = h + ((size_t)r * SLOTS + step) * DD;   // slot t-1 == step
    const float* te = te_all + (size_t)step * DD;
    for (int d = threadIdx.x; d < DD; d += blockDim.x)
        dst[d] += te[d];
}

__global__ void gather_kernel(const float* __restrict__ h, float* __restrict__ X, int t)
{
    int blk = blockIdx.x;               // b*(L*t) + (l*t + s)
    int b   = blk / (LL * t);
    int rem = blk % (LL * t);
    int l = rem / t, s = rem % t;
    const float* src = h + (((size_t)(b * LL + l)) * SLOTS + s) * DD;
    float* dst = X + ((size_t)b * (LL * t) + rem) * DD;
    for (int d = threadIdx.x; d < DD; d += blockDim.x)
        dst[d] = src[d];
}

__global__ void scatter_kernel(float* __restrict__ h, const float* __restrict__ Y, int t)
{
    int r = blockIdx.x;                 // b*L + l
    int b = r / LL, l = r % LL;
    const float* src = Y + ((size_t)b * (LL * t) + (size_t)l * t + (t - 1)) * DD;
    float* dst = h + ((size_t)r * SLOTS + t) * DD;      // append as slot t
    for (int d = threadIdx.x; d < DD; d += blockDim.x)
        dst[d] = src[d];
}

__global__ void lastgather_kernel(const float* __restrict__ h, float* __restrict__ last)
{
    int r = blockIdx.x;                 // b*L + l
    const float* src = h + ((size_t)r * SLOTS + NSTEPS) * DD;   // slot 6
    float* dst = last + (size_t)r * DD;
    for (int d = threadIdx.x; d < DD; d += blockDim.x)
        dst[d] = src[d];
}

// ---------------- tiled SGEMM: C[M,N] = A[M,K] @ W[N,K]^T + bias, optional relu ----
// 64x64 block tile, 256 threads, 4x4 microtile, BK=16.
// Assumes M % 64 == 0 and K % 16 == 0 (true for all call sites). N edge checked.
__global__ void sgemm_kernel(const float* __restrict__ A, const float* __restrict__ W,
                             const float* __restrict__ bias, float* __restrict__ Cmat,
                             int M, int N, int K, int relu)
{
    __shared__ float As[16][65];
    __shared__ float Ws[16][65];
    const int tid = threadIdx.x;
    const int m0 = blockIdx.y * 64, n0 = blockIdx.x * 64;
    const int tx = tid & 15, ty = tid >> 4;
    const int lr = tid >> 2;            // 0..63: row within tile
    const int lc = (tid & 3) << 2;      // 0,4,8,12: k offset (float4)

    float acc[4][4];
    #pragma unroll
    for (int i = 0; i < 4; i++)
        #pragma unroll
        for (int j = 0; j < 4; j++) acc[i][j] = 0.f;

    const float* Aptr = A + (size_t)(m0 + lr) * K + lc;
    const bool wvalid = (n0 + lr) < N;
    const float* Wptr = wvalid ? (W + (size_t)(n0 + lr) * K + lc) : W;

    for (int k0 = 0; k0 < K; k0 += 16) {
        float4 av = *(const float4*)(Aptr + k0);
        As[lc + 0][lr] = av.x; As[lc + 1][lr] = av.y;
        As[lc + 2][lr] = av.z; As[lc + 3][lr] = av.w;
        float4 wv = make_float4(0.f, 0.f, 0.f, 0.f);
        if (wvalid) wv = *(const float4*)(Wptr + k0);
        Ws[lc + 0][lr] = wv.x; Ws[lc + 1][lr] = wv.y;
        Ws[lc + 2][lr] = wv.z; Ws[lc + 3][lr] = wv.w;
        __syncthreads();

        #pragma unroll
        for (int kk = 0; kk < 16; kk++) {
            float a[4], bf[4];
            #pragma unroll
            for (int i = 0; i < 4; i++) a[i] = As[kk][ty * 4 + i];
            #pragma unroll
            for (int j = 0; j < 4; j++) bf[j] = Ws[kk][tx * 4 + j];
            #pragma unroll
            for (int i = 0; i < 4; i++)
                #pragma unroll
                for (int j = 0; j < 4; j++)
                    acc[i][j] = fmaf(a[i], bf[j], acc[i][j]);
        }
        __syncthreads();
    }

    #pragma unroll
    for (int i = 0; i < 4; i++) {
        int m = m0 + ty * 4 + i;
        #pragma unroll
        for (int j = 0; j < 4; j++) {
            int n = n0 + tx * 4 + j;
            if (n < N) {
                float v = acc[i][j] + bias[n];
                if (relu) v = fmaxf(v, 0.f);
                Cmat[(size_t)m * N + n] = v;
            }
        }
    }
}

// ---------------- attention: one block per (q, head, batch) ----------------
// pass 1: scores into smem (K tiles staged through smem), masked softmax
// pass 2: O = attn @ V (V tiles staged through smem)
__global__ void attention_kernel(const float* __restrict__ QKV, const int* __restrict__ amask,
                                 float* __restrict__ O, int S, int t)
{
    __shared__ float qv[HDIM];
    __shared__ float sc[SMAX];
    __shared__ float Kt[128][HDIM + 1];
    __shared__ float red[128];
    __shared__ float part[2][HDIM];

    const int q  = blockIdx.x;
    const int hh = blockIdx.y;
    const int b  = blockIdx.z;
    const int tid = threadIdx.x;        // 128 threads

    const float* Qrow = QKV + ((size_t)(b * S + q) * 3 * DD) + hh * HDIM;
    if (tid < HDIM) qv[tid] = Qrow[tid];
    __syncthreads();

    const int qblk = q / t;

    // ---- pass 1: scores ----
    for (int kb = 0; kb < S; kb += 128) {
        #pragma unroll
        for (int j = 0; j < 16; j++) {
            int idx = tid + j * 128;            // 0..2047
            int row = idx >> 4;
            int c4  = (idx & 15) << 2;
            const float* Krow = QKV + ((size_t)(b * S + kb + row) * 3 * DD) + DD + hh * HDIM;
            float4 v = *(const float4*)(Krow + c4);
            Kt[row][c4 + 0] = v.x; Kt[row][c4 + 1] = v.y;
            Kt[row][c4 + 2] = v.z; Kt[row][c4 + 3] = v.w;
        }
        __syncthreads();
        int k = kb + tid;
        int kblk = k / t;
        bool allowed = ((k % t) == 0) || (kblk == qblk);
        bool pad = (amask[b * LL + kblk] == 0);
        float sv;
        if (!allowed || pad) {
            sv = -INFINITY;
        } else {
            float dot = 0.f;
            #pragma unroll
            for (int d = 0; d < HDIM; d++) dot = fmaf(qv[d], Kt[tid][d], dot);
            sv = dot * 0.125f;                  // 1/sqrt(64)
        }
        sc[k] = sv;
        __syncthreads();
    }

    // ---- softmax ----
    float lmax = -INFINITY;
    for (int k = tid; k < S; k += 128) lmax = fmaxf(lmax, sc[k]);
    red[tid] = lmax; __syncthreads();
    for (int st = 64; st > 0; st >>= 1) {
        if (tid < st) red[tid] = fmaxf(red[tid], red[tid + st]);
        __syncthreads();
    }
    float mx = red[0];
    __syncthreads();

    float lsum = 0.f;
    for (int k = tid; k < S; k += 128) {
        float v = sc[k];
        float e = (v == -INFINITY) ? 0.f : __expf(v - mx);
        sc[k] = e;
        lsum += e;
    }
    red[tid] = lsum; __syncthreads();
    for (int st = 64; st > 0; st >>= 1) {
        if (tid < st) red[tid] += red[tid + st];
        __syncthreads();
    }
    float inv = 1.f / red[0];
    __syncthreads();

    // ---- pass 2: O = attn @ V ----
    const int d    = tid & (HDIM - 1);
    const int half = tid >> 6;
    float acc = 0.f;
    for (int kb = 0; kb < S; kb += 128) {
        #pragma unroll
        for (int j = 0; j < 16; j++) {
            int idx = tid + j * 128;
            int row = idx >> 4;
            int c4  = (idx & 15) << 2;
            const float* Vrow = QKV + ((size_t)(b * S + kb + row) * 3 * DD) + 2 * DD + hh * HDIM;
            float4 v = *(const float4*)(Vrow + c4);
            Kt[row][c4 + 0] = v.x; Kt[row][c4 + 1] = v.y;
            Kt[row][c4 + 2] = v.z; Kt[row][c4 + 3] = v.w;
        }
        __syncthreads();
        int base = half * 64;
        #pragma unroll
        for (int kk = 0; kk < 64; kk++)
            acc = fmaf(sc[kb + base + kk], Kt[base + kk][d], acc);
        __syncthreads();
    }
    part[half][d] = acc;
    __syncthreads();
    if (tid < HDIM)
        O[((size_t)(b * S + q) * DD) + hh * HDIM + tid] = (part[0][tid] + part[1][tid]) * inv;
}

// ---------------- fused residual add + LayerNorm ----------------
// out = LN(Xin + Del) * g + b, one block (256 thr) per row of 768
__global__ void addln_kernel(const float* __restrict__ Xin, const float* __restrict__ Del,
                             const float* __restrict__ g, const float* __restrict__ bta,
                             float* __restrict__ out)
{
    __shared__ float red[256];
    const int row = blockIdx.x;
    const int tid = threadIdx.x;
    const float* a  = Xin + (size_t)row * DD;
    const float* dl = Del + (size_t)row * DD;

    float v[3];
    float s = 0.f;
    #pragma unroll
    for (int i = 0; i < 3; i++) {
        int idx = tid + i * 256;
        v[i] = a[idx] + dl[idx];
        s += v[i];
    }
    red[tid] = s; __syncthreads();
    for (int st = 128; st > 0; st >>= 1) {
        if (tid < st) red[tid] += red[tid + st];
        __syncthreads();
    }
    float mean = red[0] * (1.f / DD);
    __syncthreads();

    float sq = 0.f;
    #pragma unroll
    for (int i = 0; i < 3; i++) { float dv = v[i] - mean; sq += dv * dv; }
    red[tid] = sq; __syncthreads();
    for (int st = 128; st > 0; st >>= 1) {
        if (tid < st) red[tid] += red[tid + st];
        __syncthreads();
    }
    float inv = rsqrtf(red[0] * (1.f / DD) + 1e-5f);

    float* o = out + (size_t)row * DD;
    #pragma unroll
    for (int i = 0; i < 3; i++) {
        int idx = tid + i * 256;
        o[idx] = (v[i] - mean) * inv * g[idx] + bta[idx];
    }
}

// ---------------- orchestration ----------------
extern "C" void kernel_launch(void* const* d_in, const int* in_sizes, int n_in,
                              void* d_out, int out_size)
{
    const int*   x          = (const int*)  d_in[0];
    const int*   am         = (const int*)  d_in[1];
    const float* emb        = (const float*)d_in[2];
    const float* pos        = (const float*)d_in[3];
    const float* time_emb   = (const float*)d_in[4];
    const float* in_proj_w  = (const float*)d_in[5];
    const float* in_proj_b  = (const float*)d_in[6];
    const float* attn_out_w = (const float*)d_in[7];
    const float* attn_out_b = (const float*)d_in[8];
    const float* ln1_g      = (const float*)d_in[9];
    const float* ln1_b      = (const float*)d_in[10];
    const float* w1         = (const float*)d_in[11];
    const float* b1         = (const float*)d_in[12];
    const float* w2         = (const float*)d_in[13];
    const float* b2         = (const float*)d_in[14];
    const float* ln2_g      = (const float*)d_in[15];
    const float* ln2_b      = (const float*)d_in[16];
    const float* head_w     = (const float*)d_in[17];
    const float* head_b     = (const float*)d_in[18];
    float* out = (float*)d_out;

    float *h, *X, *QKV, *AT, *X1, *F, *LAST;
    cudaGetSymbolAddress((void**)&h,    g_h);
    cudaGetSymbolAddress((void**)&X,    g_X);
    cudaGetSymbolAddress((void**)&QKV,  g_QKV);
    cudaGetSymbolAddress((void**)&AT,   g_AT);
    cudaGetSymbolAddress((void**)&X1,   g_X1);
    cudaGetSymbolAddress((void**)&F,    g_F);
    cudaGetSymbolAddress((void**)&LAST, g_LAST);

    embed_kernel<<<BB * LL, 256>>>(x, emb, pos, h);

    for (int step = 0; step < NSTEPS; step++) {
        const int t = step + 1;
        const int S = LL * t;
        const int M = BB * S;

        timeadd_kernel<<<BB * LL, 256>>>(h, time_emb, step);
        gather_kernel <<<BB * S, 256>>>(h, X, t);

        // QKV = X @ in_proj_w^T + b  :  [M, 2304]
        {
            dim3 grid((3 * DD) / 64, M / 64);
            sgemm_kernel<<<grid, 256>>>(X, in_proj_w, in_proj_b, QKV, M, 3 * DD, DD, 0);
        }
        // attention -> AT [M, 768]
        {
            dim3 grid(S, NH, BB);
            attention_kernel<<<grid, 128>>>(QKV, am, AT, S, t);
        }
        // proj: F = AT @ attn_out_w^T + b
        {
            dim3 grid(DD / 64, M / 64);
            sgemm_kernel<<<grid, 256>>>(AT, attn_out_w, attn_out_b, F, M, DD, DD, 0);
        }
        // X1 = LN(X + F)
        addln_kernel<<<M, 256>>>(X, F, ln1_g, ln1_b, X1);
        // F = relu(X1 @ w1^T + b1)
        {
            dim3 grid(DD / 64, M / 64);
            sgemm_kernel<<<grid, 256>>>(X1, w1, b1, F, M, DD, DD, 1);
        }
        // AT = F @ w2^T + b2
        {
            dim3 grid(DD / 64, M / 64);
            sgemm_kernel<<<grid, 256>>>(F, w2, b2, AT, M, DD, DD, 0);
        }
        // X = LN(X1 + AT)   (layer output)
        addln_kernel<<<M, 256>>>(X1, AT, ln2_g, ln2_b, X);

        scatter_kernel<<<BB * LL, 256>>>(h, X, t);
    }

    lastgather_kernel<<<BB * LL, 256>>>(h, LAST);

    // logits = LAST @ head_w^T + head_b : [1024, 50257]
    {
        dim3 grid((NC + 63) / 64, (BB * LL) / 64);
        sgemm_kernel<<<grid, 256>>>(LAST, head_w, head_b, out, BB * LL, NC, DD, 0);
    }
}

// round 4
// speedup vs baseline: 3.6148x; 3.6148x over previous
#include <cuda_runtime.h>
#include <math.h>
#include <stdint.h>

// ---------------- problem constants ----------------
#define BB      4
#define LL      256
#define DD      768
#define NH      12
#define HDIM    64
#define NSTEPS  6
#define SMAX    (LL * NSTEPS)      // 1536
#define NC      50257
#define SLOTS   (NSTEPS + 1)       // 7

// ---------------- device scratch ----------------
__device__ float g_h   [BB * LL * SLOTS * DD];
__device__ float g_X   [BB * SMAX * DD];
__device__ float g_QKV [BB * SMAX * 3 * DD];
__device__ float g_AT  [BB * SMAX * DD];
__device__ float g_X1  [BB * SMAX * DD];
__device__ float g_F   [BB * SMAX * DD];
__device__ float g_LAST[BB * LL * DD];

// ---------------- small elementwise kernels ----------------
__global__ void embed_kernel(const int* __restrict__ x, const float* __restrict__ emb,
                             const float* __restrict__ pos, float* __restrict__ h)
{
    int r = blockIdx.x;
    int l = r % LL;
    int tok = x[r];
    const float* e = emb + (size_t)tok * DD;
    const float* p = pos + (size_t)l * DD;
    float* dst = h + (size_t)r * SLOTS * DD;
    for (int d = threadIdx.x; d < DD; d += blockDim.x)
        dst[d] = e[d] + p[d];
}

__global__ void timeadd_kernel(float* __restrict__ h, const float* __restrict__ te_all, int step)
{
    int r = blockIdx.x;
    float* dst = h + ((size_t)r * SLOTS + step) * DD;
    const float* te = te_all + (size_t)step * DD;
    for (int d = threadIdx.x; d < DD; d += blockDim.x)
        dst[d] += te[d];
}

__global__ void gather_kernel(const float* __restrict__ h, float* __restrict__ X, int t)
{
    int blk = blockIdx.x;
    int b   = blk / (LL * t);
    int rem = blk % (LL * t);
    int l = rem / t, s = rem % t;
    const float* src = h + (((size_t)(b * LL + l)) * SLOTS + s) * DD;
    float* dst = X + ((size_t)b * (LL * t) + rem) * DD;
    for (int d = threadIdx.x; d < DD; d += blockDim.x)
        dst[d] = src[d];
}

__global__ void scatter_kernel(float* __restrict__ h, const float* __restrict__ Y, int t)
{
    int r = blockIdx.x;
    int b = r / LL, l = r % LL;
    const float* src = Y + ((size_t)b * (LL * t) + (size_t)l * t + (t - 1)) * DD;
    float* dst = h + ((size_t)r * SLOTS + t) * DD;
    for (int d = threadIdx.x; d < DD; d += blockDim.x)
        dst[d] = src[d];
}

__global__ void lastgather_kernel(const float* __restrict__ h, float* __restrict__ last)
{
    int r = blockIdx.x;
    const float* src = h + ((size_t)r * SLOTS + NSTEPS) * DD;
    float* dst = last + (size_t)r * DD;
    for (int d = threadIdx.x; d < DD; d += blockDim.x)
        dst[d] = src[d];
}

// ---------------- SGEMM v2: C[M,N] = A[M,K] @ W[N,K]^T + bias ----------------
// 128x128 block tile, BK=8, 256 threads, 8x8 microtile, double-buffered smem.
// M % 128 == 0, K % 8 == 0 guaranteed at all call sites. N edge guarded.
__global__ void sgemm128_kernel(const float* __restrict__ A, const float* __restrict__ W,
                                const float* __restrict__ bias, float* __restrict__ Cmat,
                                int M, int N, int K, int relu)
{
    __shared__ float As[2][8][128];
    __shared__ float Ws[2][8][128];

    const int tid = threadIdx.x;
    const int m0 = blockIdx.y * 128, n0 = blockIdx.x * 128;
    const int tx = tid & 15, ty = tid >> 4;
    const int lrow = tid >> 1;           // 0..127
    const int lk   = (tid & 1) * 4;      // 0 or 4

    const float* Ap = A + (size_t)(m0 + lrow) * K + lk;
    const int wrow = n0 + lrow;
    const bool wvld = wrow < N;
    const float* Wp = W + (size_t)(wvld ? wrow : 0) * K + lk;

    // preload tile 0
    {
        float4 av = *(const float4*)(Ap);
        float4 wv = wvld ? *(const float4*)(Wp) : make_float4(0.f,0.f,0.f,0.f);
        As[0][lk+0][lrow] = av.x; As[0][lk+1][lrow] = av.y;
        As[0][lk+2][lrow] = av.z; As[0][lk+3][lrow] = av.w;
        Ws[0][lk+0][lrow] = wv.x; Ws[0][lk+1][lrow] = wv.y;
        Ws[0][lk+2][lrow] = wv.z; Ws[0][lk+3][lrow] = wv.w;
    }
    __syncthreads();

    float acc[8][8];
    #pragma unroll
    for (int i = 0; i < 8; i++)
        #pragma unroll
        for (int j = 0; j < 8; j++) acc[i][j] = 0.f;

    int buf = 0;
    const int nIter = K >> 3;
    for (int it = 0; it < nIter; it++) {
        const int k0n = (it + 1) << 3;
        const bool hasNext = k0n < K;
        float4 an, wn;
        if (hasNext) {
            an = *(const float4*)(Ap + k0n);
            wn = wvld ? *(const float4*)(Wp + k0n) : make_float4(0.f,0.f,0.f,0.f);
        }

        #pragma unroll
        for (int kk = 0; kk < 8; kk++) {
            float a[8], b[8];
            *(float4*)&a[0] = *(const float4*)&As[buf][kk][ty * 4];
            *(float4*)&a[4] = *(const float4*)&As[buf][kk][64 + ty * 4];
            *(float4*)&b[0] = *(const float4*)&Ws[buf][kk][tx * 4];
            *(float4*)&b[4] = *(const float4*)&Ws[buf][kk][64 + tx * 4];
            #pragma unroll
            for (int i = 0; i < 8; i++)
                #pragma unroll
                for (int j = 0; j < 8; j++)
                    acc[i][j] = fmaf(a[i], b[j], acc[i][j]);
        }

        if (hasNext) {
            int nb = buf ^ 1;
            As[nb][lk+0][lrow] = an.x; As[nb][lk+1][lrow] = an.y;
            As[nb][lk+2][lrow] = an.z; As[nb][lk+3][lrow] = an.w;
            Ws[nb][lk+0][lrow] = wn.x; Ws[nb][lk+1][lrow] = wn.y;
            Ws[nb][lk+2][lrow] = wn.z; Ws[nb][lk+3][lrow] = wn.w;
            __syncthreads();
            buf = nb;
        }
    }

    #pragma unroll
    for (int i = 0; i < 8; i++) {
        int m = m0 + ((i < 4) ? (ty * 4 + i) : (64 + ty * 4 + i - 4));
        float* Crow = Cmat + (size_t)m * N;
        #pragma unroll
        for (int j = 0; j < 8; j++) {
            int n = n0 + ((j < 4) ? (tx * 4 + j) : (64 + tx * 4 + j - 4));
            if (n < N) {
                float v = acc[i][j] + bias[n];
                if (relu) v = fmaxf(v, 0.f);
                Crow[n] = v;
            }
        }
    }
}

// ---------------- sparse attention exploiting the thoughts mask ----------------
// Allowed keys for query q (step t): {j*t : j=0..255} ∪ {qblk*t+s : s=1..t-1}.
// Block handles QT=16 queries for one (b, h). 256 threads: (qi = tid/16, ki = tid%16).
#define QT 16
#define SCW 272
__global__ void attn_sparse_kernel(const float* __restrict__ QKV, const int* __restrict__ amask,
                                   float* __restrict__ O, int S, int t)
{
    __shared__ float Qs [QT][68];
    __shared__ float KVs[16][68];
    __shared__ float Sc [QT][SCW];

    const int q0 = blockIdx.x * QT;
    const int hh = blockIdx.y;
    const int b  = blockIdx.z;
    const int tid = threadIdx.x;
    const int qi = tid >> 4;
    const int ki = tid & 15;

    const float* base = QKV + (size_t)b * S * 3 * DD;

    // load Q tile (float4, stride-68 rows are 16B-aligned per row? use scalar-safe path)
    {
        const float* Qrow = base + (size_t)(q0 + qi) * 3 * DD + hh * HDIM;
        float4 v = *(const float4*)(Qrow + ki * 4);
        Qs[qi][ki*4+0] = v.x; Qs[qi][ki*4+1] = v.y;
        Qs[qi][ki*4+2] = v.z; Qs[qi][ki*4+3] = v.w;
    }
    __syncthreads();

    // ---- line-key scores ----
    for (int jc = 0; jc < LL; jc += 16) {
        const float* Krow = base + (size_t)((jc + qi) * t) * 3 * DD + DD + hh * HDIM;
        float4 v = *(const float4*)(Krow + ki * 4);
        KVs[qi][ki*4+0] = v.x; KVs[qi][ki*4+1] = v.y;
        KVs[qi][ki*4+2] = v.z; KVs[qi][ki*4+3] = v.w;
        __syncthreads();

        float dot = 0.f;
        #pragma unroll
        for (int d = 0; d < HDIM; d++)
            dot = fmaf(Qs[qi][d], KVs[ki][d], dot);
        int j = jc + ki;
        bool pad = (amask[b * LL + j] == 0);
        Sc[qi][j] = pad ? -INFINITY : dot * 0.125f;
        __syncthreads();
    }

    // ---- same-block key scores (s = 1..t-1) ----
    if (ki >= 1 && ki < t) {
        int q = q0 + qi;
        int qblk = q / t;
        const float* Krow = base + (size_t)(qblk * t + ki) * 3 * DD + DD + hh * HDIM;
        float dot = 0.f;
        #pragma unroll
        for (int d = 0; d < HDIM; d++)
            dot = fmaf(Qs[qi][d], Krow[d], dot);
        bool pad = (amask[b * LL + qblk] == 0);
        Sc[qi][LL + ki - 1] = pad ? -INFINITY : dot * 0.125f;
    }
    __syncthreads();

    // ---- softmax over nk = 256 + t - 1 entries, 16 lanes per row ----
    const int nk = LL + t - 1;
    float mx = -INFINITY;
    for (int j = ki; j < nk; j += 16) mx = fmaxf(mx, Sc[qi][j]);
    #pragma unroll
    for (int o = 8; o > 0; o >>= 1)
        mx = fmaxf(mx, __shfl_xor_sync(0xffffffffu, mx, o, 16));

    float sum = 0.f;
    for (int j = ki; j < nk; j += 16) {
        float v = Sc[qi][j];
        float e = (v == -INFINITY) ? 0.f : __expf(v - mx);
        Sc[qi][j] = e;
        sum += e;
    }
    #pragma unroll
    for (int o = 8; o > 0; o >>= 1)
        sum += __shfl_xor_sync(0xffffffffu, sum, o, 16);
    const float inv = 1.f / sum;
    __syncthreads();

    // ---- AV: thread (qi, ki) accumulates dims ki*4..ki*4+3 of query qi ----
    float4 acc = make_float4(0.f, 0.f, 0.f, 0.f);
    for (int jc = 0; jc < LL; jc += 16) {
        const float* Vrow = base + (size_t)((jc + qi) * t) * 3 * DD + 2 * DD + hh * HDIM;
        float4 v = *(const float4*)(Vrow + ki * 4);
        KVs[qi][ki*4+0] = v.x; KVs[qi][ki*4+1] = v.y;
        KVs[qi][ki*4+2] = v.z; KVs[qi][ki*4+3] = v.w;
        __syncthreads();

        #pragma unroll
        for (int kk = 0; kk < 16; kk++) {
            float p = Sc[qi][jc + kk];
            acc.x = fmaf(p, KVs[kk][ki*4+0], acc.x);
            acc.y = fmaf(p, KVs[kk][ki*4+1], acc.y);
            acc.z = fmaf(p, KVs[kk][ki*4+2], acc.z);
            acc.w = fmaf(p, KVs[kk][ki*4+3], acc.w);
        }
        __syncthreads();
    }

    // same-block V contributions
    {
        int q = q0 + qi;
        int qblk = q / t;
        for (int s = 1; s < t; s++) {
            float p = Sc[qi][LL + s - 1];
            const float* Vrow = base + (size_t)(qblk * t + s) * 3 * DD + 2 * DD + hh * HDIM;
            float4 v = *(const float4*)(Vrow + ki * 4);
            acc.x = fmaf(p, v.x, acc.x);
            acc.y = fmaf(p, v.y, acc.y);
            acc.z = fmaf(p, v.z, acc.z);
            acc.w = fmaf(p, v.w, acc.w);
        }
    }

    float* Orow = O + (size_t)(b * S + q0 + qi) * DD + hh * HDIM + ki * 4;
    Orow[0] = acc.x * inv;
    Orow[1] = acc.y * inv;
    Orow[2] = acc.z * inv;
    Orow[3] = acc.w * inv;
}

// ---------------- fused residual add + LayerNorm ----------------
__global__ void addln_kernel(const float* __restrict__ Xin, const float* __restrict__ Del,
                             const float* __restrict__ g, const float* __restrict__ bta,
                             float* __restrict__ out)
{
    __shared__ float red[256];
    const int row = blockIdx.x;
    const int tid = threadIdx.x;
    const float* a  = Xin + (size_t)row * DD;
    const float* dl = Del + (size_t)row * DD;

    float v[3];
    float s = 0.f;
    #pragma unroll
    for (int i = 0; i < 3; i++) {
        int idx = tid + i * 256;
        v[i] = a[idx] + dl[idx];
        s += v[i];
    }
    red[tid] = s; __syncthreads();
    for (int st = 128; st > 0; st >>= 1) {
        if (tid < st) red[tid] += red[tid + st];
        __syncthreads();
    }
    float mean = red[0] * (1.f / DD);
    __syncthreads();

    float sq = 0.f;
    #pragma unroll
    for (int i = 0; i < 3; i++) { float dv = v[i] - mean; sq += dv * dv; }
    red[tid] = sq; __syncthreads();
    for (int st = 128; st > 0; st >>= 1) {
        if (tid < st) red[tid] += red[tid + st];
        __syncthreads();
    }
    float inv = rsqrtf(red[0] * (1.f / DD) + 1e-5f);

    float* o = out + (size_t)row * DD;
    #pragma unroll
    for (int i = 0; i < 3; i++) {
        int idx = tid + i * 256;
        o[idx] = (v[i] - mean) * inv * g[idx] + bta[idx];
    }
}

// ---------------- orchestration ----------------
extern "C" void kernel_launch(void* const* d_in, const int* in_sizes, int n_in,
                              void* d_out, int out_size)
{
    const int*   x          = (const int*)  d_in[0];
    const int*   am         = (const int*)  d_in[1];
    const float* emb        = (const float*)d_in[2];
    const float* pos        = (const float*)d_in[3];
    const float* time_emb   = (const float*)d_in[4];
    const float* in_proj_w  = (const float*)d_in[5];
    const float* in_proj_b  = (const float*)d_in[6];
    const float* attn_out_w = (const float*)d_in[7];
    const float* attn_out_b = (const float*)d_in[8];
    const float* ln1_g      = (const float*)d_in[9];
    const float* ln1_b      = (const float*)d_in[10];
    const float* w1         = (const float*)d_in[11];
    const float* b1         = (const float*)d_in[12];
    const float* w2         = (const float*)d_in[13];
    const float* b2         = (const float*)d_in[14];
    const float* ln2_g      = (const float*)d_in[15];
    const float* ln2_b      = (const float*)d_in[16];
    const float* head_w     = (const float*)d_in[17];
    const float* head_b     = (const float*)d_in[18];
    float* out = (float*)d_out;

    float *h, *X, *QKV, *AT, *X1, *F, *LAST;
    cudaGetSymbolAddress((void**)&h,    g_h);
    cudaGetSymbolAddress((void**)&X,    g_X);
    cudaGetSymbolAddress((void**)&QKV,  g_QKV);
    cudaGetSymbolAddress((void**)&AT,   g_AT);
    cudaGetSymbolAddress((void**)&X1,   g_X1);
    cudaGetSymbolAddress((void**)&F,    g_F);
    cudaGetSymbolAddress((void**)&LAST, g_LAST);

    embed_kernel<<<BB * LL, 256>>>(x, emb, pos, h);

    for (int step = 0; step < NSTEPS; step++) {
        const int t = step + 1;
        const int S = LL * t;
        const int M = BB * S;

        timeadd_kernel<<<BB * LL, 256>>>(h, time_emb, step);
        gather_kernel <<<BB * S, 256>>>(h, X, t);

        {   // QKV = X @ in_proj_w^T + b : [M, 2304]
            dim3 grid((3 * DD) / 128, M / 128);
            sgemm128_kernel<<<grid, 256>>>(X, in_proj_w, in_proj_b, QKV, M, 3 * DD, DD, 0);
        }
        {   // sparse attention -> AT [M, 768]
            dim3 grid(S / QT, NH, BB);
            attn_sparse_kernel<<<grid, 256>>>(QKV, am, AT, S, t);
        }
        {   // proj
            dim3 grid(DD / 128, M / 128);
            sgemm128_kernel<<<grid, 256>>>(AT, attn_out_w, attn_out_b, F, M, DD, DD, 0);
        }
        addln_kernel<<<M, 256>>>(X, F, ln1_g, ln1_b, X1);
        {   // ff1 + relu
            dim3 grid(DD / 128, M / 128);
            sgemm128_kernel<<<grid, 256>>>(X1, w1, b1, F, M, DD, DD, 1);
        }
        {   // ff2
            dim3 grid(DD / 128, M / 128);
            sgemm128_kernel<<<grid, 256>>>(F, w2, b2, AT, M, DD, DD, 0);
        }
        addln_kernel<<<M, 256>>>(X1, AT, ln2_g, ln2_b, X);

        scatter_kernel<<<BB * LL, 256>>>(h, X, t);
    }

    lastgather_kernel<<<BB * LL, 256>>>(h, LAST);

    {   // logits = LAST @ head_w^T + head_b : [1024, 50257]
        dim3 grid((NC + 127) / 128, (BB * LL) / 128);
        sgemm128_kernel<<<grid, 256>>>(LAST, head_w, head_b, out, BB * LL, NC, DD, 0);
    }
}